// round 1
// baseline (speedup 1.0000x reference)
#include <cuda_runtime.h>
#include <math.h>

#define Bn    2
#define Nn    384
#define HIDn  128
#define NHn   8
#define HDn   16
#define HROWS (Bn*Nn)          // 768
#define EROWS (Bn*Nn*Nn)       // 294912

// ---------------- scratch (static device globals; no allocations) ----------------
__device__ float g_h0[HROWS*HIDn];
__device__ float g_Q[HROWS*HIDn];
__device__ float g_K[HROWS*HIDn];
__device__ float g_V[HROWS*HIDn];
__device__ float g_eatt[(size_t)EROWS*NHn];   // (b,i,j,h) contiguous h
__device__ float g_amean[EROWS];
__device__ float g_attO[HROWS*HIDn];
__device__ float g_hW[HROWS*HIDn];

// ---------------- kernel 1: h0 = node @ W_node + b_node ----------------
__global__ void k_lin_h0(const float* __restrict__ X, const float* __restrict__ W,
                         const float* __restrict__ bias) {
  int d = threadIdx.x;            // 128
  int r0 = blockIdx.x * 8;        // 96 blocks
  __shared__ float sX[8*128];
  for (int idx = d; idx < 8*128; idx += 128) sX[idx] = X[r0*128 + idx];
  __syncthreads();
  float acc[8];
  float bv = bias[d];
#pragma unroll
  for (int r = 0; r < 8; r++) acc[r] = bv;
  for (int k = 0; k < 128; k++) {
    float w = W[k*128 + d];
#pragma unroll
    for (int r = 0; r < 8; r++) acc[r] += sX[r*128 + k] * w;
  }
#pragma unroll
  for (int r = 0; r < 8; r++) g_h0[(r0 + r)*128 + d] = acc[r];
}

// ---------------- kernel 2: Q,K,V = h0 @ {Wq,Wk,Wv} + bias ----------------
__global__ void k_qkv(const float* __restrict__ Wq, const float* __restrict__ bq,
                      const float* __restrict__ Wk, const float* __restrict__ bk,
                      const float* __restrict__ Wv, const float* __restrict__ bv) {
  int d = threadIdx.x;
  int r0 = blockIdx.x * 8;
  __shared__ float sX[8*128];
  for (int idx = d; idx < 8*128; idx += 128) sX[idx] = g_h0[r0*128 + idx];
  __syncthreads();
  float aq[8], ak[8], av[8];
  float bqv = bq[d], bkv = bk[d], bvv = bv[d];
#pragma unroll
  for (int r = 0; r < 8; r++) { aq[r] = bqv; ak[r] = bkv; av[r] = bvv; }
  for (int k = 0; k < 128; k++) {
    float wq = Wq[k*128 + d], wk = Wk[k*128 + d], wv = Wv[k*128 + d];
#pragma unroll
    for (int r = 0; r < 8; r++) {
      float x = sX[r*128 + k];
      aq[r] += x*wq; ak[r] += x*wk; av[r] += x*wv;
    }
  }
#pragma unroll
  for (int r = 0; r < 8; r++) {
    g_Q[(r0 + r)*128 + d] = aq[r];
    g_K[(r0 + r)*128 + d] = ak[r];
    g_V[(r0 + r)*128 + d] = av[r];
  }
}

// ---------------- kernel 3: edge_attn[b,i,j,h] = sum_d (E@We+be)*(sigmoid(E@Wg+bg)) ----------------
// Fused GEMM-reduce: never materializes the two (B,N,N,128) intermediates (2x151MB saved).
#define TILE_R 64
#define TPB    4   // row-tiles per block
__global__ void k_edge_attn(const float* __restrict__ E,
                            const float* __restrict__ We, const float* __restrict__ be,
                            const float* __restrict__ Wg, const float* __restrict__ bg) {
  extern __shared__ float sm[];
  float* sW = sm;                 // [128][256]  (We cols 0..127 | Wg cols 128..255)
  float* sE = sm + 128*256;       // [64][128]
  int tid = threadIdx.x;          // 512
  for (int idx = tid; idx < 128*128; idx += 512) {
    int k = idx >> 7, d = idx & 127;
    sW[k*256 + d]       = We[idx];
    sW[k*256 + 128 + d] = Wg[idx];
  }
  int cg = tid & 31;              // column group: dims d0..d0+3
  int rg = tid >> 5;              // row group: rows r0..r0+3
  int d0 = cg * 4;
  float bE[4], bG[4];
#pragma unroll
  for (int t = 0; t < 4; t++) { bE[t] = be[d0 + t]; bG[t] = bg[d0 + t]; }
  int head = cg >> 2;             // 4 dims per thread, all inside one 16-dim head
  bool writer = ((cg & 3) == 0);

  for (int tile = 0; tile < TPB; tile++) {
    long rowBase = ((long)blockIdx.x * TPB + tile) * TILE_R;
    __syncthreads();
    {
      const float4* Ev = (const float4*)(E + rowBase * 128);
      float4* sEv = (float4*)sE;
      for (int idx = tid; idx < (64*128)/4; idx += 512) sEv[idx] = Ev[idx];
    }
    __syncthreads();
    float aE[4][4], aG[4][4];
#pragma unroll
    for (int r = 0; r < 4; r++)
#pragma unroll
      for (int dd = 0; dd < 4; dd++) { aE[r][dd] = 0.f; aG[r][dd] = 0.f; }
    const float* sErow = sE + rg*4*128;
#pragma unroll 4
    for (int k = 0; k < 128; k++) {
      float4 we4 = *(const float4*)(sW + k*256 + d0);
      float4 wg4 = *(const float4*)(sW + k*256 + 128 + d0);
      float ev[4];
      ev[0] = sErow[k]; ev[1] = sErow[128 + k]; ev[2] = sErow[256 + k]; ev[3] = sErow[384 + k];
      float wE[4] = { we4.x, we4.y, we4.z, we4.w };
      float wG[4] = { wg4.x, wg4.y, wg4.z, wg4.w };
#pragma unroll
      for (int r = 0; r < 4; r++)
#pragma unroll
        for (int dd = 0; dd < 4; dd++) {
          aE[r][dd] += ev[r] * wE[dd];
          aG[r][dd] += ev[r] * wG[dd];
        }
    }
    // gated reduce epilogue: s = sum_dd eh * sigmoid(eg), reduced over 4 lanes per head
#pragma unroll
    for (int r = 0; r < 4; r++) {
      float s = 0.f;
#pragma unroll
      for (int dd = 0; dd < 4; dd++) {
        float eh = aE[r][dd] + bE[dd];
        float eg = aG[r][dd] + bG[dd];
        s += eh / (1.f + __expf(-eg));
      }
      s += __shfl_xor_sync(0xffffffffu, s, 1);
      s += __shfl_xor_sync(0xffffffffu, s, 2);
      if (writer) g_eatt[(size_t)(rowBase + rg*4 + r)*NHn + head] = s;
    }
  }
}

// ---------------- kernel 4: scores + mask + softmax + attn_mean + attn_out ----------------
__global__ void k_attn(const int* __restrict__ adj) {
  int bi = blockIdx.x;            // b*N + i  (768 blocks)
  int b  = bi / Nn;
  int t  = threadIdx.x;           // 384 threads (one per j)
  int lane = t & 31, w = t >> 5;  // 12 warps
  __shared__ float sQ[128];
  __shared__ float sAtt[NHn*Nn];  // [h][j]
  __shared__ float sRed[12*NHn];
  __shared__ float gMax[NHn];
  __shared__ float gSum[NHn];
  __shared__ float sPart[3*128];
  if (t < 128) sQ[t] = g_Q[bi*128 + t];
  __syncthreads();
  int j = t;
  float s[NHn];
  {
    const float* Krow = g_K + (b*Nn + j)*128;
    const float* er   = g_eatt + ((size_t)bi*Nn + j)*NHn;
#pragma unroll
    for (int h = 0; h < NHn; h++) {
      float acc = 0.f;
#pragma unroll
      for (int d = 0; d < HDn; d++) acc += sQ[h*16 + d] * Krow[h*16 + d];
      s[h] = acc * 0.25f + er[h];
    }
  }
  if (adj[(long)bi*Nn + j] == 0) {
#pragma unroll
    for (int h = 0; h < NHn; h++) s[h] = -1e9f;
  }
  // block max per head
  float red[NHn];
#pragma unroll
  for (int h = 0; h < NHn; h++) red[h] = s[h];
#pragma unroll
  for (int off = 16; off > 0; off >>= 1)
#pragma unroll
    for (int h = 0; h < NHn; h++) red[h] = fmaxf(red[h], __shfl_xor_sync(0xffffffffu, red[h], off));
  if (lane == 0)
#pragma unroll
    for (int h = 0; h < NHn; h++) sRed[w*NHn + h] = red[h];
  __syncthreads();
  if (t < NHn) {
    float m = -1e30f;
    for (int ww = 0; ww < 12; ww++) m = fmaxf(m, sRed[ww*NHn + t]);
    gMax[t] = m;
  }
  __syncthreads();
  float p[NHn];
#pragma unroll
  for (int h = 0; h < NHn; h++) p[h] = __expf(s[h] - gMax[h]);
  // block sum per head
#pragma unroll
  for (int h = 0; h < NHn; h++) red[h] = p[h];
#pragma unroll
  for (int off = 16; off > 0; off >>= 1)
#pragma unroll
    for (int h = 0; h < NHn; h++) red[h] += __shfl_xor_sync(0xffffffffu, red[h], off);
  if (lane == 0)
#pragma unroll
    for (int h = 0; h < NHn; h++) sRed[w*NHn + h] = red[h];
  __syncthreads();
  if (t < NHn) {
    float m = 0.f;
    for (int ww = 0; ww < 12; ww++) m += sRed[ww*NHn + t];
    gSum[t] = m;
  }
  __syncthreads();
  float am = 0.f;
#pragma unroll
  for (int h = 0; h < NHn; h++) {
    float a = p[h] / gSum[h];
    sAtt[h*Nn + j] = a;
    am += a;
  }
  g_amean[(long)bi*Nn + j] = am * (1.f/NHn);
  __syncthreads();
  // attn_out[b,i,h,d] = sum_j attn[h,j] * V[b,j,h,d]
  {
    int d = t & 127;
    int jg = t >> 7;              // 0..2
    int h = d >> 4;
    float acc = 0.f;
    for (int jj = jg; jj < Nn; jj += 3)
      acc += sAtt[h*Nn + jj] * g_V[(b*Nn + jj)*128 + d];
    sPart[jg*128 + d] = acc;
  }
  __syncthreads();
  if (t < 128) g_attO[bi*128 + t] = sPart[t] + sPart[128 + t] + sPart[256 + t];
}

// ---------------- kernel 5: h = LN(h0 + attO@W_out + b_out); hW = h @ W_eout ----------------
__global__ void k_hout(const float* __restrict__ Wout, const float* __restrict__ bout,
                       const float* __restrict__ g1, const float* __restrict__ be1,
                       const float* __restrict__ Weout, float* __restrict__ outH) {
  int row = blockIdx.x;           // 768
  int d = threadIdx.x;            // 128
  int lane = d & 31, w = d >> 5;
  __shared__ float sIn[128];
  __shared__ float sRow[128];
  __shared__ float sS[4], sQ2[4];
  sIn[d] = g_attO[row*128 + d];
  __syncthreads();
  float acc = bout[d];
#pragma unroll 4
  for (int k = 0; k < 128; k++) acc += sIn[k] * Wout[k*128 + d];
  float r = acc + g_h0[row*128 + d];
  float v = r, q = r*r;
#pragma unroll
  for (int off = 16; off > 0; off >>= 1) {
    v += __shfl_xor_sync(0xffffffffu, v, off);
    q += __shfl_xor_sync(0xffffffffu, q, off);
  }
  if (lane == 0) { sS[w] = v; sQ2[w] = q; }
  __syncthreads();
  float tot  = sS[0] + sS[1] + sS[2] + sS[3];
  float totq = sQ2[0] + sQ2[1] + sQ2[2] + sQ2[3];
  float mean = tot * (1.f/128.f);
  float var  = totq * (1.f/128.f) - mean*mean;
  float y = (r - mean) * rsqrtf(var + 1e-5f) * g1[d] + be1[d];
  outH[row*128 + d] = y;
  sRow[d] = y;
  __syncthreads();
  float acc2 = 0.f;
#pragma unroll 4
  for (int k = 0; k < 128; k++) acc2 += sRow[k] * Weout[k*128 + d];
  g_hW[row*128 + d] = acc2;
}

// ---------------- kernel 6: edge_out = LN(E + amean*0.5*(hW_i+hW_j) + b_eout) ----------------
__global__ void k_edge_out(const float* __restrict__ Ef, const float* __restrict__ beout,
                           const float* __restrict__ g2, const float* __restrict__ be2,
                           float* __restrict__ outE) {
  int warp = threadIdx.x >> 5, lane = threadIdx.x & 31;
  long row = (long)blockIdx.x * 8 + warp;   // < EROWS
  int b  = (int)(row / (Nn*Nn));
  int ij = (int)(row % (Nn*Nn));
  int i = ij / Nn, j = ij % Nn;
  float am = g_amean[row] * 0.5f;
  float4 e  = ((const float4*)(Ef + row*128))[lane];
  float4 ui = ((const float4*)(g_hW + (b*Nn + i)*128))[lane];
  float4 uj = ((const float4*)(g_hW + (b*Nn + j)*128))[lane];
  float4 bo = ((const float4*)beout)[lane];
  float v0 = e.x + am*(ui.x + uj.x) + bo.x;
  float v1 = e.y + am*(ui.y + uj.y) + bo.y;
  float v2 = e.z + am*(ui.z + uj.z) + bo.z;
  float v3 = e.w + am*(ui.w + uj.w) + bo.w;
  float s = v0 + v1 + v2 + v3;
  float q = v0*v0 + v1*v1 + v2*v2 + v3*v3;
#pragma unroll
  for (int off = 16; off > 0; off >>= 1) {
    s += __shfl_xor_sync(0xffffffffu, s, off);
    q += __shfl_xor_sync(0xffffffffu, q, off);
  }
  float mean = s * (1.f/128.f);
  float var  = q * (1.f/128.f) - mean*mean;
  float inv  = rsqrtf(var + 1e-5f);
  float4 gg = ((const float4*)g2)[lane];
  float4 bb = ((const float4*)be2)[lane];
  float4 o;
  o.x = (v0 - mean)*inv*gg.x + bb.x;
  o.y = (v1 - mean)*inv*gg.y + bb.y;
  o.z = (v2 - mean)*inv*gg.z + bb.z;
  o.w = (v3 - mean)*inv*gg.w + bb.w;
  ((float4*)outE)[row*32 + lane] = o;
}

// ---------------- launcher ----------------
extern "C" void kernel_launch(void* const* d_in, const int* in_sizes, int n_in,
                              void* d_out, int out_size) {
  const float* node   = (const float*)d_in[0];
  const float* edge   = (const float*)d_in[1];
  const int*   adj    = (const int*)  d_in[2];
  const float* W_node = (const float*)d_in[3];  const float* b_node = (const float*)d_in[4];
  const float* W_q    = (const float*)d_in[5];  const float* b_q    = (const float*)d_in[6];
  const float* W_k    = (const float*)d_in[7];  const float* b_k    = (const float*)d_in[8];
  const float* W_v    = (const float*)d_in[9];  const float* b_v    = (const float*)d_in[10];
  const float* W_edge = (const float*)d_in[11]; const float* b_edge = (const float*)d_in[12];
  const float* W_gate = (const float*)d_in[13]; const float* b_gate = (const float*)d_in[14];
  const float* W_out  = (const float*)d_in[15]; const float* b_out  = (const float*)d_in[16];
  const float* W_eout = (const float*)d_in[17]; const float* b_eout = (const float*)d_in[18];
  const float* g1     = (const float*)d_in[19]; const float* be1    = (const float*)d_in[20];
  const float* g2     = (const float*)d_in[21]; const float* be2    = (const float*)d_in[22];

  float* outH = (float*)d_out;                 // (B,N,HID)
  float* outE = outH + HROWS*HIDn;             // (B,N,N,EDGE_DIM)

  // 160KB dynamic smem for the fused edge GEMM (host-side attr set; not a stream op)
  cudaFuncSetAttribute(k_edge_attn, cudaFuncAttributeMaxDynamicSharedMemorySize, 164*1024);

  k_lin_h0<<<HROWS/8, 128>>>(node, W_node, b_node);
  k_qkv<<<HROWS/8, 128>>>(W_q, b_q, W_k, b_k, W_v, b_v);
  k_edge_attn<<<EROWS/(TILE_R*TPB), 512, (128*256 + 64*128)*4>>>(edge, W_edge, b_edge, W_gate, b_gate);
  k_attn<<<HROWS, 384>>>(adj);
  k_hout<<<HROWS, 128>>>(W_out, b_out, g1, be1, W_eout, outH);
  k_edge_out<<<EROWS/8, 256>>>(edge, b_eout, g2, be2, outE);
}

// round 3
// speedup vs baseline: 2.1250x; 2.1250x over previous
#include <cuda_runtime.h>
#include <cstdint>
#include <math.h>

#define Bn    2
#define Nn    384
#define HIDn  128
#define NHn   8
#define HDn   16
#define HROWS (Bn*Nn)          // 768
#define EROWS (Bn*Nn*Nn)       // 294912

// ---------------- scratch (static device globals; no allocations) ----------------
__device__ float g_h0[HROWS*HIDn];
__device__ float g_Q[HROWS*HIDn];
__device__ float g_K[HROWS*HIDn];
__device__ float g_V[HROWS*HIDn];
__device__ float g_eatt[(size_t)EROWS*NHn];   // (b,i,j,h) contiguous h
__device__ float g_amean[EROWS];
__device__ float g_attO[HROWS*HIDn];
__device__ float g_hW[HROWS*HIDn];

// ================= helpers =================
__device__ __forceinline__ uint32_t f2tf32(float f) {
  uint32_t r;
  asm("cvt.rna.tf32.f32 %0, %1;" : "=r"(r) : "f"(f));
  return r;
}
__device__ __forceinline__ void mma8(float* d, const uint32_t* a, float2 bv) {
  uint32_t b0 = __float_as_uint(bv.x), b1 = __float_as_uint(bv.y);
  asm volatile("mma.sync.aligned.m16n8k8.row.col.f32.tf32.tf32.f32 "
    "{%0,%1,%2,%3},{%4,%5,%6,%7},{%8,%9},{%0,%1,%2,%3};"
    : "+f"(d[0]), "+f"(d[1]), "+f"(d[2]), "+f"(d[3])
    : "r"(a[0]), "r"(a[1]), "r"(a[2]), "r"(a[3]), "r"(b0), "r"(b1));
}
__device__ __forceinline__ float sigm(float x) { return 1.f / (1.f + __expf(-x)); }

// ---------------- kernel 1: h0 = node @ W_node + b_node ----------------
__global__ void k_lin_h0(const float* __restrict__ X, const float* __restrict__ W,
                         const float* __restrict__ bias) {
  int d = threadIdx.x;
  int r0 = blockIdx.x * 8;
  __shared__ float sX[8*128];
  for (int idx = d; idx < 8*128; idx += 128) sX[idx] = X[r0*128 + idx];
  __syncthreads();
  float acc[8];
  float bv = bias[d];
#pragma unroll
  for (int r = 0; r < 8; r++) acc[r] = bv;
  for (int k = 0; k < 128; k++) {
    float w = W[k*128 + d];
#pragma unroll
    for (int r = 0; r < 8; r++) acc[r] += sX[r*128 + k] * w;
  }
#pragma unroll
  for (int r = 0; r < 8; r++) g_h0[(r0 + r)*128 + d] = acc[r];
}

// ---------------- kernel 2: Q,K,V ----------------
__global__ void k_qkv(const float* __restrict__ Wq, const float* __restrict__ bq,
                      const float* __restrict__ Wk, const float* __restrict__ bk,
                      const float* __restrict__ Wv, const float* __restrict__ bv) {
  int d = threadIdx.x;
  int r0 = blockIdx.x * 8;
  __shared__ float sX[8*128];
  for (int idx = d; idx < 8*128; idx += 128) sX[idx] = g_h0[r0*128 + idx];
  __syncthreads();
  float aq[8], ak[8], av[8];
  float bqv = bq[d], bkv = bk[d], bvv = bv[d];
#pragma unroll
  for (int r = 0; r < 8; r++) { aq[r] = bqv; ak[r] = bkv; av[r] = bvv; }
  for (int k = 0; k < 128; k++) {
    float wq = Wq[k*128 + d], wk = Wk[k*128 + d], wv = Wv[k*128 + d];
#pragma unroll
    for (int r = 0; r < 8; r++) {
      float x = sX[r*128 + k];
      aq[r] += x*wq; ak[r] += x*wk; av[r] += x*wv;
    }
  }
#pragma unroll
  for (int r = 0; r < 8; r++) {
    g_Q[(r0 + r)*128 + d] = aq[r];
    g_K[(r0 + r)*128 + d] = ak[r];
    g_V[(r0 + r)*128 + d] = av[r];
  }
}

// ---------------- kernel 3: edge_attn via mma.sync tf32 ----------------
// Computes, per E-row: eatt[h] = sum_d (E@We + be)[h*16+d] * sigmoid((E@Wg + bg)[h*16+d]).
// A (E tile, 128x128) and B (We/Wg, transposed) are pre-packed into SMEM in
// m16n8k8 fragment order: one LDS.128 per A-frag, one LDS.64 per B-frag.
#define EA_GRID 144
#define EA_TPC  16
#define EA_SMEM ((32768 + 16384 + 256) * 4)   // B-pack | A-pack | biases

__global__ void __launch_bounds__(256, 1) k_edge_attn_mma(
    const float* __restrict__ E,
    const float* __restrict__ We, const float* __restrict__ Wg,
    const float* __restrict__ be, const float* __restrict__ bg) {
  extern __shared__ float sm[];
  uint32_t* sB = (uint32_t*)sm;           // 32768: [pass][ks 16][nt 16][lane 32][reg 2]
  uint32_t* sA = (uint32_t*)(sm + 32768); // 16384: [ks 16][mt 8][lane 32][reg 4]
  float*    sBias = sm + 32768 + 16384;   // 256: be | bg
  int tid = threadIdx.x;
  int wid = tid >> 5, lane = tid & 31;

  if (tid < 128) { sBias[tid] = be[tid]; sBias[128 + tid] = bg[tid]; }

  // Stage B pack (both weights), converting fp32 -> tf32 (rna)
  for (int idx = tid; idx < 32768; idx += 256) {
    int reg = idx & 1, l2 = (idx >> 1) & 31, nt = (idx >> 6) & 15, ks = (idx >> 10) & 15, pass = idx >> 14;
    int n = nt*8 + (l2 >> 2);
    int k = ks*8 + (l2 & 3) + reg*4;
    const float* W = pass ? Wg : We;
    sB[idx] = f2tf32(W[k*128 + n]);
  }
  __syncthreads();

  const float2* sBv = (const float2*)sB;
  int t4 = lane & 3;

  for (int t = 0; t < EA_TPC; t++) {
    size_t rowBase = ((size_t)blockIdx.x * EA_TPC + t) * 128;
    __syncthreads();   // previous tile's compute done before overwriting sA
    // Stage A tile in fragment order
    const float4* Eg = (const float4*)(E + rowBase*128);
    for (int idx = tid; idx < 4096; idx += 256) {
      int m = idx >> 5, c4 = idx & 31;
      float4 v = Eg[idx];
      int ks = c4 >> 1, hi = (c4 & 1) * 2, mt = m >> 4, rb = (m >> 3) & 1;
      int base = ((ks*8 + mt)*32 + (m & 7)*4) * 4 + rb + hi;
      sA[base + 0*4] = f2tf32(v.x);
      sA[base + 1*4] = f2tf32(v.y);
      sA[base + 2*4] = f2tf32(v.z);
      sA[base + 3*4] = f2tf32(v.w);
    }
    __syncthreads();

    const uint4* sAv = (const uint4*)sA;
#pragma unroll
    for (int hg = 0; hg < 2; hg++) {
      float aE[4][2][4], aG[4][2][4];
#pragma unroll
      for (int h2 = 0; h2 < 4; h2++)
#pragma unroll
        for (int n2 = 0; n2 < 2; n2++)
#pragma unroll
          for (int r = 0; r < 4; r++) { aE[h2][n2][r] = 0.f; aG[h2][n2][r] = 0.f; }
      for (int ks = 0; ks < 16; ks++) {
        uint4 av = sAv[(ks*8 + wid)*32 + lane];
        uint32_t a[4] = { av.x, av.y, av.z, av.w };
#pragma unroll
        for (int h2 = 0; h2 < 4; h2++) {
          int h = hg*4 + h2;
#pragma unroll
          for (int n2 = 0; n2 < 2; n2++) {
            int nt = h*2 + n2;
            float2 bE = sBv[(ks*16 + nt)*32 + lane];
            mma8(aE[h2][n2], a, bE);
            float2 bG = sBv[((16 + ks)*16 + nt)*32 + lane];
            mma8(aG[h2][n2], a, bG);
          }
        }
      }
      // epilogue: bias + sigmoid gate + reduce 16 dims per head
#pragma unroll
      for (int h2 = 0; h2 < 4; h2++) {
        int h = hg*4 + h2;
        float s0 = 0.f, s1 = 0.f;
#pragma unroll
        for (int n2 = 0; n2 < 2; n2++) {
          int cb = h*16 + n2*8 + 2*t4;
          float be0 = sBias[cb], be1 = sBias[cb + 1];
          float bg0 = sBias[128 + cb], bg1 = sBias[128 + cb + 1];
          s0 += (aE[h2][n2][0] + be0) * sigm(aG[h2][n2][0] + bg0)
              + (aE[h2][n2][1] + be1) * sigm(aG[h2][n2][1] + bg1);
          s1 += (aE[h2][n2][2] + be0) * sigm(aG[h2][n2][2] + bg0)
              + (aE[h2][n2][3] + be1) * sigm(aG[h2][n2][3] + bg1);
        }
        s0 += __shfl_xor_sync(0xffffffffu, s0, 1);
        s0 += __shfl_xor_sync(0xffffffffu, s0, 2);
        s1 += __shfl_xor_sync(0xffffffffu, s1, 1);
        s1 += __shfl_xor_sync(0xffffffffu, s1, 2);
        if (t4 == 0) {
          size_t row0 = rowBase + wid*16 + (lane >> 2);
          g_eatt[row0*8 + h]       = s0;
          g_eatt[(row0 + 8)*8 + h] = s1;
        }
      }
    }
  }
}

// ---------------- kernel 4: scores + softmax + attn_mean + attn_out (tiled) ----------------
#define IPB 4
#define KPAD 132
__global__ void __launch_bounds__(256) k_attn2(const int* __restrict__ adj) {
  extern __shared__ float sm2[];
  float* sQ    = sm2;                   // IPB*128
  float* sPart = sQ + IPB*128;          // IPB*128
  float* sKV   = sPart + IPB*128;       // 64*KPAD
  float* sAtt  = sKV + 64*KPAD;         // IPB*8*Nn
  int tid = threadIdx.x;
  int bi0 = blockIdx.x * IPB;
  int b = bi0 / Nn;

  for (int idx = tid; idx < IPB*128; idx += 256) sQ[idx] = g_Q[bi0*128 + idx];
  __syncthreads();

  // Phase A: scores
  int jl = tid & 63, hp = tid >> 6;
  int h0 = hp*2;
  for (int jt = 0; jt < Nn/64; jt++) {
    for (int idx = tid; idx < 64*32; idx += 256) {
      int r = idx >> 5, c4 = idx & 31;
      float4 v = ((const float4*)(g_K + (size_t)(b*Nn + jt*64)*128))[idx];
      *(float4*)(sKV + r*KPAD + c4*4) = v;
    }
    __syncthreads();
    int j = jt*64 + jl;
    const float* kr = sKV + jl*KPAD;
    float a0[IPB], a1[IPB];
#pragma unroll
    for (int q = 0; q < IPB; q++) { a0[q] = 0.f; a1[q] = 0.f; }
#pragma unroll
    for (int d = 0; d < 16; d++) {
      float k0 = kr[h0*16 + d], k1 = kr[h0*16 + 16 + d];
#pragma unroll
      for (int q = 0; q < IPB; q++) {
        a0[q] += sQ[q*128 + h0*16 + d]      * k0;
        a1[q] += sQ[q*128 + h0*16 + 16 + d] * k1;
      }
    }
#pragma unroll
    for (int q = 0; q < IPB; q++) {
      int bi = bi0 + q;
      const float* er = g_eatt + ((size_t)bi*Nn + j)*8 + h0;
      float sc0 = a0[q]*0.25f + er[0];
      float sc1 = a1[q]*0.25f + er[1];
      if (adj[(size_t)bi*Nn + j] == 0) { sc0 = -1e9f; sc1 = -1e9f; }
      sAtt[(q*8 + h0)*Nn + j]     = sc0;
      sAtt[(q*8 + h0 + 1)*Nn + j] = sc1;
    }
    __syncthreads();
  }

  // Phase B: softmax (warp h owns head h)
  {
    int w = tid >> 5, lane = tid & 31;
    if (w < NHn) {
      for (int q = 0; q < IPB; q++) {
        float* rowp = sAtt + (q*8 + w)*Nn;
        float vals[12];
        float m = -1e30f;
#pragma unroll
        for (int c = 0; c < 12; c++) { vals[c] = rowp[lane + c*32]; m = fmaxf(m, vals[c]); }
#pragma unroll
        for (int off = 16; off > 0; off >>= 1) m = fmaxf(m, __shfl_xor_sync(0xffffffffu, m, off));
        float s = 0.f;
#pragma unroll
        for (int c = 0; c < 12; c++) { vals[c] = __expf(vals[c] - m); s += vals[c]; }
#pragma unroll
        for (int off = 16; off > 0; off >>= 1) s += __shfl_xor_sync(0xffffffffu, s, off);
        float inv = 1.f / s;
#pragma unroll
        for (int c = 0; c < 12; c++) rowp[lane + c*32] = vals[c] * inv;
      }
    }
  }
  __syncthreads();

  // attn_mean
  for (int idx = tid; idx < IPB*Nn; idx += 256) {
    int q = idx / Nn, j = idx % Nn;
    float s = 0.f;
#pragma unroll
    for (int h = 0; h < 8; h++) s += sAtt[(q*8 + h)*Nn + j];
    g_amean[(size_t)(bi0 + q)*Nn + j] = s * (1.f/NHn);
  }

  // Phase C: attn_out
  int d = tid & 127, half = tid >> 7;
  int hc = d >> 4;
  float acc[IPB];
#pragma unroll
  for (int q = 0; q < IPB; q++) acc[q] = 0.f;
  for (int jt = 0; jt < Nn/64; jt++) {
    __syncthreads();
    for (int idx = tid; idx < 64*32; idx += 256) {
      int r = idx >> 5, c4 = idx & 31;
      float4 v = ((const float4*)(g_V + (size_t)(b*Nn + jt*64)*128))[idx];
      *(float4*)(sKV + r*KPAD + c4*4) = v;
    }
    __syncthreads();
#pragma unroll 8
    for (int jj = half*32; jj < half*32 + 32; jj++) {
      float v = sKV[jj*KPAD + d];
      int j = jt*64 + jj;
#pragma unroll
      for (int q = 0; q < IPB; q++) acc[q] += sAtt[(q*8 + hc)*Nn + j] * v;
    }
  }
  __syncthreads();
  if (half == 1) {
#pragma unroll
    for (int q = 0; q < IPB; q++) sPart[q*128 + d] = acc[q];
  }
  __syncthreads();
  if (half == 0) {
#pragma unroll
    for (int q = 0; q < IPB; q++)
      g_attO[(size_t)(bi0 + q)*128 + d] = acc[q] + sPart[q*128 + d];
  }
}

// ---------------- kernel 5: h = LN(h0 + attO@W_out + b_out); hW = h @ W_eout ----------------
__global__ void k_hout(const float* __restrict__ Wout, const float* __restrict__ bout,
                       const float* __restrict__ g1, const float* __restrict__ be1,
                       const float* __restrict__ Weout, float* __restrict__ outH) {
  int row = blockIdx.x;
  int d = threadIdx.x;
  int lane = d & 31, w = d >> 5;
  __shared__ float sIn[128];
  __shared__ float sRow[128];
  __shared__ float sS[4], sQ2[4];
  sIn[d] = g_attO[row*128 + d];
  __syncthreads();
  float acc = bout[d];
#pragma unroll 4
  for (int k = 0; k < 128; k++) acc += sIn[k] * Wout[k*128 + d];
  float r = acc + g_h0[row*128 + d];
  float v = r, q = r*r;
#pragma unroll
  for (int off = 16; off > 0; off >>= 1) {
    v += __shfl_xor_sync(0xffffffffu, v, off);
    q += __shfl_xor_sync(0xffffffffu, q, off);
  }
  if (lane == 0) { sS[w] = v; sQ2[w] = q; }
  __syncthreads();
  float tot  = sS[0] + sS[1] + sS[2] + sS[3];
  float totq = sQ2[0] + sQ2[1] + sQ2[2] + sQ2[3];
  float mean = tot * (1.f/128.f);
  float var  = totq * (1.f/128.f) - mean*mean;
  float y = (r - mean) * rsqrtf(var + 1e-5f) * g1[d] + be1[d];
  outH[row*128 + d] = y;
  sRow[d] = y;
  __syncthreads();
  float acc2 = 0.f;
#pragma unroll 4
  for (int k = 0; k < 128; k++) acc2 += sRow[k] * Weout[k*128 + d];
  g_hW[row*128 + d] = acc2;
}

// ---------------- kernel 6: edge_out = LN(E + amean*0.5*(hW_i+hW_j) + b_eout) ----------------
__global__ void k_edge_out(const float* __restrict__ Ef, const float* __restrict__ beout,
                           const float* __restrict__ g2, const float* __restrict__ be2,
                           float* __restrict__ outE) {
  int warp = threadIdx.x >> 5, lane = threadIdx.x & 31;
  size_t row = (size_t)blockIdx.x * 8 + warp;
  int b  = (int)(row / (Nn*Nn));
  int ij = (int)(row % (Nn*Nn));
  int i = ij / Nn, j = ij % Nn;
  float am = g_amean[row] * 0.5f;
  float4 e  = ((const float4*)(Ef + row*128))[lane];
  float4 ui = ((const float4*)(g_hW + (size_t)(b*Nn + i)*128))[lane];
  float4 uj = ((const float4*)(g_hW + (size_t)(b*Nn + j)*128))[lane];
  float4 bo = ((const float4*)beout)[lane];
  float v0 = e.x + am*(ui.x + uj.x) + bo.x;
  float v1 = e.y + am*(ui.y + uj.y) + bo.y;
  float v2 = e.z + am*(ui.z + uj.z) + bo.z;
  float v3 = e.w + am*(ui.w + uj.w) + bo.w;
  float s = v0 + v1 + v2 + v3;
  float q = v0*v0 + v1*v1 + v2*v2 + v3*v3;
#pragma unroll
  for (int off = 16; off > 0; off >>= 1) {
    s += __shfl_xor_sync(0xffffffffu, s, off);
    q += __shfl_xor_sync(0xffffffffu, q, off);
  }
  float mean = s * (1.f/128.f);
  float var  = q * (1.f/128.f) - mean*mean;
  float inv  = rsqrtf(var + 1e-5f);
  float4 gg = ((const float4*)g2)[lane];
  float4 bb = ((const float4*)be2)[lane];
  float4 o;
  o.x = (v0 - mean)*inv*gg.x + bb.x;
  o.y = (v1 - mean)*inv*gg.y + bb.y;
  o.z = (v2 - mean)*inv*gg.z + bb.z;
  o.w = (v3 - mean)*inv*gg.w + bb.w;
  ((float4*)outE)[row*32 + lane] = o;
}

// ---------------- launcher ----------------
extern "C" void kernel_launch(void* const* d_in, const int* in_sizes, int n_in,
                              void* d_out, int out_size) {
  const float* node   = (const float*)d_in[0];
  const float* edge   = (const float*)d_in[1];
  const int*   adj    = (const int*)  d_in[2];
  const float* W_node = (const float*)d_in[3];  const float* b_node = (const float*)d_in[4];
  const float* W_q    = (const float*)d_in[5];  const float* b_q    = (const float*)d_in[6];
  const float* W_k    = (const float*)d_in[7];  const float* b_k    = (const float*)d_in[8];
  const float* W_v    = (const float*)d_in[9];  const float* b_v    = (const float*)d_in[10];
  const float* W_edge = (const float*)d_in[11]; const float* b_edge = (const float*)d_in[12];
  const float* W_gate = (const float*)d_in[13]; const float* b_gate = (const float*)d_in[14];
  const float* W_out  = (const float*)d_in[15]; const float* b_out  = (const float*)d_in[16];
  const float* W_eout = (const float*)d_in[17]; const float* b_eout = (const float*)d_in[18];
  const float* g1     = (const float*)d_in[19]; const float* be1    = (const float*)d_in[20];
  const float* g2     = (const float*)d_in[21]; const float* be2    = (const float*)d_in[22];

  float* outH = (float*)d_out;
  float* outE = outH + HROWS*HIDn;

  cudaFuncSetAttribute(k_edge_attn_mma, cudaFuncAttributeMaxDynamicSharedMemorySize, EA_SMEM);
  cudaFuncSetAttribute(k_attn2, cudaFuncAttributeMaxDynamicSharedMemorySize, 128*1024);

  int attn_smem = (IPB*128 + IPB*128 + 64*KPAD + IPB*8*Nn) * 4;

  k_lin_h0<<<HROWS/8, 128>>>(node, W_node, b_node);
  k_qkv<<<HROWS/8, 128>>>(W_q, b_q, W_k, b_k, W_v, b_v);
  k_edge_attn_mma<<<EA_GRID, 256, EA_SMEM>>>(edge, W_edge, W_gate, b_edge, b_gate);
  k_attn2<<<HROWS/IPB, 256, attn_smem>>>(adj);
  k_hout<<<HROWS, 128>>>(W_out, b_out, g1, be1, W_eout, outH);
  k_edge_out<<<EROWS/8, 256>>>(edge, b_eout, g2, be2, outE);
}

// round 4
// speedup vs baseline: 2.7832x; 1.3097x over previous
#include <cuda_runtime.h>
#include <cstdint>
#include <math.h>

#define Bn    2
#define Nn    384
#define HIDn  128
#define NHn   8
#define HDn   16
#define HROWS (Bn*Nn)          // 768
#define EROWS (Bn*Nn*Nn)       // 294912

// ---------------- scratch (static device globals; no allocations) ----------------
__device__ float g_h0[HROWS*HIDn];
__device__ float g_Q[HROWS*HIDn];
__device__ float g_K[HROWS*HIDn];
__device__ float g_V[HROWS*HIDn];
__device__ float g_eatt[(size_t)EROWS*NHn];   // (b,i,j,h) contiguous h
__device__ float g_amean[EROWS];
__device__ float g_attO[HROWS*HIDn];
__device__ float g_hW[HROWS*HIDn];

// ================= helpers =================
__device__ __forceinline__ float sigm(float x) { return 1.f / (1.f + __expf(-x)); }
__device__ __forceinline__ uint32_t pack_half2(float lo, float hi) {
  uint32_t r;
  asm("cvt.rn.f16x2.f32 %0, %1, %2;" : "=r"(r) : "f"(hi), "f"(lo));
  return r;
}
__device__ __forceinline__ void mma16(float* d, const uint4 a, const uint2 b) {
  asm volatile("mma.sync.aligned.m16n8k16.row.col.f32.f16.f16.f32 "
    "{%0,%1,%2,%3},{%4,%5,%6,%7},{%8,%9},{%0,%1,%2,%3};"
    : "+f"(d[0]), "+f"(d[1]), "+f"(d[2]), "+f"(d[3])
    : "r"(a.x), "r"(a.y), "r"(a.z), "r"(a.w), "r"(b.x), "r"(b.y));
}
__device__ __forceinline__ uint32_t smem_u32(const void* p) {
  uint32_t a;
  asm("{ .reg .u64 t; cvta.to.shared.u64 t, %1; cvt.u32.u64 %0, t; }" : "=r"(a) : "l"(p));
  return a;
}
__device__ __forceinline__ void cpa16(uint32_t dst, const void* src) {
  asm volatile("cp.async.cg.shared.global [%0], [%1], 16;" :: "r"(dst), "l"(src));
}
#define CPA_COMMIT() asm volatile("cp.async.commit_group;" ::: "memory")
#define CPA_WAIT0()  asm volatile("cp.async.wait_group 0;" ::: "memory")

// ---------------- kernel 1: h0 = node @ W_node + b_node ----------------
__global__ void k_lin_h0(const float* __restrict__ X, const float* __restrict__ W,
                         const float* __restrict__ bias) {
  int d = threadIdx.x;
  int r0 = blockIdx.x * 8;
  __shared__ float sX[8*128];
  for (int idx = d; idx < 8*128; idx += 128) sX[idx] = X[r0*128 + idx];
  __syncthreads();
  float acc[8];
  float bv = bias[d];
#pragma unroll
  for (int r = 0; r < 8; r++) acc[r] = bv;
  for (int k = 0; k < 128; k++) {
    float w = W[k*128 + d];
#pragma unroll
    for (int r = 0; r < 8; r++) acc[r] += sX[r*128 + k] * w;
  }
#pragma unroll
  for (int r = 0; r < 8; r++) g_h0[(r0 + r)*128 + d] = acc[r];
}

// ---------------- kernel 2: Q,K,V ----------------
__global__ void k_qkv(const float* __restrict__ Wq, const float* __restrict__ bq,
                      const float* __restrict__ Wk, const float* __restrict__ bk,
                      const float* __restrict__ Wv, const float* __restrict__ bv) {
  int d = threadIdx.x;
  int r0 = blockIdx.x * 8;
  __shared__ float sX[8*128];
  for (int idx = d; idx < 8*128; idx += 128) sX[idx] = g_h0[r0*128 + idx];
  __syncthreads();
  float aq[8], ak[8], av[8];
  float bqv = bq[d], bkv = bk[d], bvv = bv[d];
#pragma unroll
  for (int r = 0; r < 8; r++) { aq[r] = bqv; ak[r] = bkv; av[r] = bvv; }
  for (int k = 0; k < 128; k++) {
    float wq = Wq[k*128 + d], wk = Wk[k*128 + d], wv = Wv[k*128 + d];
#pragma unroll
    for (int r = 0; r < 8; r++) {
      float x = sX[r*128 + k];
      aq[r] += x*wq; ak[r] += x*wk; av[r] += x*wv;
    }
  }
#pragma unroll
  for (int r = 0; r < 8; r++) {
    g_Q[(r0 + r)*128 + d] = aq[r];
    g_K[(r0 + r)*128 + d] = ak[r];
    g_V[(r0 + r)*128 + d] = av[r];
  }
}

// ---------------- kernel 3: edge_attn via fp16 m16n8k16 mma.sync ----------------
// Per E-row: eatt[h] = sum_d (E@We + be)[h*16+d] * sigmoid((E@Wg + bg)[h*16+d]).
// cp.async double-step pipeline: raw fp32 tile (stride-132 padded) -> fragment-order
// fp16 sA (XOR-ks swizzled). B (both weights) packed once per CTA in fragment order.
#define EA_GRID 144
#define EA_TPC  16
// smem: sB 64KB | sA 32KB | raw 67584B | bias 1KB
#define EA_OFF_SA   65536
#define EA_OFF_RAW  (65536 + 32768)
#define EA_OFF_BIAS (65536 + 32768 + 67584)
#define EA_SMEM     (EA_OFF_BIAS + 1024)
#define RAW_STRIDE  132

__global__ void __launch_bounds__(256, 1) k_edge_attn_mma(
    const float* __restrict__ E,
    const float* __restrict__ We, const float* __restrict__ Wg,
    const float* __restrict__ be, const float* __restrict__ bg) {
  extern __shared__ char smem[];
  uint2* sB2   = (uint2*)smem;                    // [(ks*32+nt)*32+lane] : {b0,b1}
  uint4* sA4   = (uint4*)(smem + EA_OFF_SA);      // [((ks*8+mt)*32+lane)^ks] : {a0..a3}
  float* raw   = (float*)(smem + EA_OFF_RAW);     // [128][RAW_STRIDE]
  float* sBias = (float*)(smem + EA_OFF_BIAS);    // be | bg
  uint32_t rawu = smem_u32(raw);

  int tid = threadIdx.x;
  int wid = tid >> 5, lane = tid & 31;
  int g = lane >> 2, t4 = lane & 3;
  int mtp = wid & 3, hh = wid >> 2;

  if (tid < 128) { sBias[tid] = be[tid]; sBias[128 + tid] = bg[tid]; }

  // ---- one-time B packing (two passes through raw) ----
#pragma unroll
  for (int half = 0; half < 2; half++) {
    const float* W = half ? Wg : We;
    __syncthreads();
    for (int idx = tid; idx < 128*32; idx += 256) {
      int k = idx >> 5, c4 = idx & 31;
      float4 v = ((const float4*)W)[idx];
      *(float4*)(raw + k*RAW_STRIDE + c4*4) = v;
    }
    __syncthreads();
    for (int idx = tid; idx < 4096; idx += 256) {
      int lf = idx & 31, nt16 = (idx >> 5) & 15, ks = idx >> 9;
      int gg = lf >> 2, tt = lf & 3;
      int n = nt16*8 + gg;
      int k0 = ks*16 + 2*tt;
      uint32_t b0 = pack_half2(raw[k0*RAW_STRIDE + n],     raw[(k0+1)*RAW_STRIDE + n]);
      uint32_t b1 = pack_half2(raw[(k0+8)*RAW_STRIDE + n], raw[(k0+9)*RAW_STRIDE + n]);
      sB2[(ks*32 + half*16 + nt16)*32 + lf] = make_uint2(b0, b1);
    }
  }
  __syncthreads();

  // ---- pipeline: prefetch tile 0 ----
  {
    const float* Eg = E + ((size_t)blockIdx.x * EA_TPC) * 128 * 128;
    for (int idx = tid; idx < 4096; idx += 256) {
      int m = idx >> 5, c4 = idx & 31;
      cpa16(rawu + (uint32_t)(m*RAW_STRIDE + c4*4)*4u, Eg + m*128 + c4*4);
    }
    CPA_COMMIT();
  }

  for (int t = 0; t < EA_TPC; t++) {
    size_t rowBase = ((size_t)blockIdx.x * EA_TPC + t) * 128;
    CPA_WAIT0();
    __syncthreads();   // raw ready; previous compute done with sA

    // convert raw fp32 -> fragment-order fp16 sA (XOR-ks swizzle)
    for (int it = 0; it < 8; it++) {
      int idx = tid + it*256;                 // 0..2047
      int lf = idx & 31, mt = (idx >> 5) & 7, ks = idx >> 8;
      int gg = lf >> 2, tt = lf & 3;
      int m0 = mt*16 + gg;
      int k0 = ks*16 + 2*tt;
      float2 x0 = *(float2*)(raw + m0*RAW_STRIDE + k0);
      float2 x1 = *(float2*)(raw + (m0+8)*RAW_STRIDE + k0);
      float2 x2 = *(float2*)(raw + m0*RAW_STRIDE + k0 + 8);
      float2 x3 = *(float2*)(raw + (m0+8)*RAW_STRIDE + k0 + 8);
      uint4 v;
      v.x = pack_half2(x0.x, x0.y);
      v.y = pack_half2(x1.x, x1.y);
      v.z = pack_half2(x2.x, x2.y);
      v.w = pack_half2(x3.x, x3.y);
      sA4[idx ^ ks] = v;
    }
    __syncthreads();   // sA ready; raw free

    if (t + 1 < EA_TPC) {
      const float* Eg = E + (rowBase + 128) * 128;
      for (int idx = tid; idx < 4096; idx += 256) {
        int m = idx >> 5, c4 = idx & 31;
        cpa16(rawu + (uint32_t)(m*RAW_STRIDE + c4*4)*4u, Eg + m*128 + c4*4);
      }
      CPA_COMMIT();
    }

    // ---- compute: 2 passes (head-pair per warp per pass) ----
#pragma unroll
    for (int p = 0; p < 2; p++) {
      int hp = hh*2 + p;                      // head pair: heads 2hp, 2hp+1
      float aE[2][4][4], aG[2][4][4];
#pragma unroll
      for (int mt = 0; mt < 2; mt++)
#pragma unroll
        for (int nti = 0; nti < 4; nti++)
#pragma unroll
          for (int r = 0; r < 4; r++) { aE[mt][nti][r] = 0.f; aG[mt][nti][r] = 0.f; }

#pragma unroll
      for (int ks = 0; ks < 8; ks++) {
        uint4 av0 = sA4[(((ks*8 + mtp*2 + 0)*32) + lane) ^ ks];
        uint4 av1 = sA4[(((ks*8 + mtp*2 + 1)*32) + lane) ^ ks];
#pragma unroll
        for (int nti = 0; nti < 4; nti++) {
          uint2 bE = sB2[(ks*32 + 4*hp + nti)*32 + lane];
          mma16(aE[0][nti], av0, bE);
          mma16(aE[1][nti], av1, bE);
          uint2 bG = sB2[(ks*32 + 16 + 4*hp + nti)*32 + lane];
          mma16(aG[0][nti], av0, bG);
          mma16(aG[1][nti], av1, bG);
        }
      }

      // epilogue: bias + sigmoid gate + per-head reduce
#pragma unroll
      for (int mt = 0; mt < 2; mt++) {
#pragma unroll
        for (int hh2 = 0; hh2 < 2; hh2++) {
          int h = 2*hp + hh2;
          float s0 = 0.f, s1 = 0.f;
#pragma unroll
          for (int n2 = 0; n2 < 2; n2++) {
            int nti = hh2*2 + n2;
            int nb = (4*hp + nti)*8 + 2*t4;
            float be0 = sBias[nb], be1 = sBias[nb+1];
            float bg0 = sBias[128+nb], bg1 = sBias[128+nb+1];
            s0 += (aE[mt][nti][0] + be0) * sigm(aG[mt][nti][0] + bg0)
                + (aE[mt][nti][1] + be1) * sigm(aG[mt][nti][1] + bg1);
            s1 += (aE[mt][nti][2] + be0) * sigm(aG[mt][nti][2] + bg0)
                + (aE[mt][nti][3] + be1) * sigm(aG[mt][nti][3] + bg1);
          }
          s0 += __shfl_xor_sync(0xffffffffu, s0, 1);
          s0 += __shfl_xor_sync(0xffffffffu, s0, 2);
          s1 += __shfl_xor_sync(0xffffffffu, s1, 1);
          s1 += __shfl_xor_sync(0xffffffffu, s1, 2);
          if (t4 == 0) {
            size_t r0 = rowBase + (size_t)(mtp*2 + mt)*16 + g;
            g_eatt[r0*8 + h]       = s0;
            g_eatt[(r0 + 8)*8 + h] = s1;
          }
        }
      }
    }
  }
}

// ---------------- kernel 4: scores + softmax + attn_mean + attn_out (tiled) ----------------
#define IPB 4
#define KPAD 132
__global__ void __launch_bounds__(256) k_attn2(const int* __restrict__ adj) {
  extern __shared__ float sm2[];
  float* sQ    = sm2;                   // IPB*128
  float* sPart = sQ + IPB*128;          // IPB*128
  float* sKV   = sPart + IPB*128;       // 64*KPAD
  float* sAtt  = sKV + 64*KPAD;         // IPB*8*Nn
  int tid = threadIdx.x;
  int bi0 = blockIdx.x * IPB;
  int b = bi0 / Nn;

  for (int idx = tid; idx < IPB*128; idx += 256) sQ[idx] = g_Q[bi0*128 + idx];
  __syncthreads();

  int jl = tid & 63, hp = tid >> 6;
  int h0 = hp*2;
  for (int jt = 0; jt < Nn/64; jt++) {
    for (int idx = tid; idx < 64*32; idx += 256) {
      int r = idx >> 5, c4 = idx & 31;
      float4 v = ((const float4*)(g_K + (size_t)(b*Nn + jt*64)*128))[idx];
      *(float4*)(sKV + r*KPAD + c4*4) = v;
    }
    __syncthreads();
    int j = jt*64 + jl;
    const float* kr = sKV + jl*KPAD;
    float a0[IPB], a1[IPB];
#pragma unroll
    for (int q = 0; q < IPB; q++) { a0[q] = 0.f; a1[q] = 0.f; }
#pragma unroll
    for (int d = 0; d < 16; d++) {
      float k0 = kr[h0*16 + d], k1 = kr[h0*16 + 16 + d];
#pragma unroll
      for (int q = 0; q < IPB; q++) {
        a0[q] += sQ[q*128 + h0*16 + d]      * k0;
        a1[q] += sQ[q*128 + h0*16 + 16 + d] * k1;
      }
    }
#pragma unroll
    for (int q = 0; q < IPB; q++) {
      int bi = bi0 + q;
      const float* er = g_eatt + ((size_t)bi*Nn + j)*8 + h0;
      float sc0 = a0[q]*0.25f + er[0];
      float sc1 = a1[q]*0.25f + er[1];
      if (adj[(size_t)bi*Nn + j] == 0) { sc0 = -1e9f; sc1 = -1e9f; }
      sAtt[(q*8 + h0)*Nn + j]     = sc0;
      sAtt[(q*8 + h0 + 1)*Nn + j] = sc1;
    }
    __syncthreads();
  }

  {
    int w = tid >> 5, lane = tid & 31;
    if (w < NHn) {
      for (int q = 0; q < IPB; q++) {
        float* rowp = sAtt + (q*8 + w)*Nn;
        float vals[12];
        float m = -1e30f;
#pragma unroll
        for (int c = 0; c < 12; c++) { vals[c] = rowp[lane + c*32]; m = fmaxf(m, vals[c]); }
#pragma unroll
        for (int off = 16; off > 0; off >>= 1) m = fmaxf(m, __shfl_xor_sync(0xffffffffu, m, off));
        float s = 0.f;
#pragma unroll
        for (int c = 0; c < 12; c++) { vals[c] = __expf(vals[c] - m); s += vals[c]; }
#pragma unroll
        for (int off = 16; off > 0; off >>= 1) s += __shfl_xor_sync(0xffffffffu, s, off);
        float inv = 1.f / s;
#pragma unroll
        for (int c = 0; c < 12; c++) rowp[lane + c*32] = vals[c] * inv;
      }
    }
  }
  __syncthreads();

  for (int idx = tid; idx < IPB*Nn; idx += 256) {
    int q = idx / Nn, j = idx % Nn;
    float s = 0.f;
#pragma unroll
    for (int h = 0; h < 8; h++) s += sAtt[(q*8 + h)*Nn + j];
    g_amean[(size_t)(bi0 + q)*Nn + j] = s * (1.f/NHn);
  }

  int d = tid & 127, half = tid >> 7;
  int hc = d >> 4;
  float acc[IPB];
#pragma unroll
  for (int q = 0; q < IPB; q++) acc[q] = 0.f;
  for (int jt = 0; jt < Nn/64; jt++) {
    __syncthreads();
    for (int idx = tid; idx < 64*32; idx += 256) {
      int r = idx >> 5, c4 = idx & 31;
      float4 v = ((const float4*)(g_V + (size_t)(b*Nn + jt*64)*128))[idx];
      *(float4*)(sKV + r*KPAD + c4*4) = v;
    }
    __syncthreads();
#pragma unroll 8
    for (int jj = half*32; jj < half*32 + 32; jj++) {
      float v = sKV[jj*KPAD + d];
      int j = jt*64 + jj;
#pragma unroll
      for (int q = 0; q < IPB; q++) acc[q] += sAtt[(q*8 + hc)*Nn + j] * v;
    }
  }
  __syncthreads();
  if (half == 1) {
#pragma unroll
    for (int q = 0; q < IPB; q++) sPart[q*128 + d] = acc[q];
  }
  __syncthreads();
  if (half == 0) {
#pragma unroll
    for (int q = 0; q < IPB; q++)
      g_attO[(size_t)(bi0 + q)*128 + d] = acc[q] + sPart[q*128 + d];
  }
}

// ---------------- kernel 5: h = LN(h0 + attO@W_out + b_out); hW = h @ W_eout ----------------
__global__ void k_hout(const float* __restrict__ Wout, const float* __restrict__ bout,
                       const float* __restrict__ g1, const float* __restrict__ be1,
                       const float* __restrict__ Weout, float* __restrict__ outH) {
  int row = blockIdx.x;
  int d = threadIdx.x;
  int lane = d & 31, w = d >> 5;
  __shared__ float sIn[128];
  __shared__ float sRow[128];
  __shared__ float sS[4], sQ2[4];
  sIn[d] = g_attO[row*128 + d];
  __syncthreads();
  float acc = bout[d];
#pragma unroll 4
  for (int k = 0; k < 128; k++) acc += sIn[k] * Wout[k*128 + d];
  float r = acc + g_h0[row*128 + d];
  float v = r, q = r*r;
#pragma unroll
  for (int off = 16; off > 0; off >>= 1) {
    v += __shfl_xor_sync(0xffffffffu, v, off);
    q += __shfl_xor_sync(0xffffffffu, q, off);
  }
  if (lane == 0) { sS[w] = v; sQ2[w] = q; }
  __syncthreads();
  float tot  = sS[0] + sS[1] + sS[2] + sS[3];
  float totq = sQ2[0] + sQ2[1] + sQ2[2] + sQ2[3];
  float mean = tot * (1.f/128.f);
  float var  = totq * (1.f/128.f) - mean*mean;
  float y = (r - mean) * rsqrtf(var + 1e-5f) * g1[d] + be1[d];
  outH[row*128 + d] = y;
  sRow[d] = y;
  __syncthreads();
  float acc2 = 0.f;
#pragma unroll 4
  for (int k = 0; k < 128; k++) acc2 += sRow[k] * Weout[k*128 + d];
  g_hW[row*128 + d] = acc2;
}

// ---------------- kernel 6: edge_out = LN(E + amean*0.5*(hW_i+hW_j) + b_eout) ----------------
__global__ void k_edge_out(const float* __restrict__ Ef, const float* __restrict__ beout,
                           const float* __restrict__ g2, const float* __restrict__ be2,
                           float* __restrict__ outE) {
  int warp = threadIdx.x >> 5, lane = threadIdx.x & 31;
  size_t row = (size_t)blockIdx.x * 8 + warp;
  int b  = (int)(row / (Nn*Nn));
  int ij = (int)(row % (Nn*Nn));
  int i = ij / Nn, j = ij % Nn;
  float am = g_amean[row] * 0.5f;
  float4 e  = ((const float4*)(Ef + row*128))[lane];
  float4 ui = ((const float4*)(g_hW + (size_t)(b*Nn + i)*128))[lane];
  float4 uj = ((const float4*)(g_hW + (size_t)(b*Nn + j)*128))[lane];
  float4 bo = ((const float4*)beout)[lane];
  float v0 = e.x + am*(ui.x + uj.x) + bo.x;
  float v1 = e.y + am*(ui.y + uj.y) + bo.y;
  float v2 = e.z + am*(ui.z + uj.z) + bo.z;
  float v3 = e.w + am*(ui.w + uj.w) + bo.w;
  float s = v0 + v1 + v2 + v3;
  float q = v0*v0 + v1*v1 + v2*v2 + v3*v3;
#pragma unroll
  for (int off = 16; off > 0; off >>= 1) {
    s += __shfl_xor_sync(0xffffffffu, s, off);
    q += __shfl_xor_sync(0xffffffffu, q, off);
  }
  float mean = s * (1.f/128.f);
  float var  = q * (1.f/128.f) - mean*mean;
  float inv  = rsqrtf(var + 1e-5f);
  float4 gg = ((const float4*)g2)[lane];
  float4 bb = ((const float4*)be2)[lane];
  float4 o;
  o.x = (v0 - mean)*inv*gg.x + bb.x;
  o.y = (v1 - mean)*inv*gg.y + bb.y;
  o.z = (v2 - mean)*inv*gg.z + bb.z;
  o.w = (v3 - mean)*inv*gg.w + bb.w;
  ((float4*)outE)[row*32 + lane] = o;
}

// ---------------- launcher ----------------
extern "C" void kernel_launch(void* const* d_in, const int* in_sizes, int n_in,
                              void* d_out, int out_size) {
  const float* node   = (const float*)d_in[0];
  const float* edge   = (const float*)d_in[1];
  const int*   adj    = (const int*)  d_in[2];
  const float* W_node = (const float*)d_in[3];  const float* b_node = (const float*)d_in[4];
  const float* W_q    = (const float*)d_in[5];  const float* b_q    = (const float*)d_in[6];
  const float* W_k    = (const float*)d_in[7];  const float* b_k    = (const float*)d_in[8];
  const float* W_v    = (const float*)d_in[9];  const float* b_v    = (const float*)d_in[10];
  const float* W_edge = (const float*)d_in[11]; const float* b_edge = (const float*)d_in[12];
  const float* W_gate = (const float*)d_in[13]; const float* b_gate = (const float*)d_in[14];
  const float* W_out  = (const float*)d_in[15]; const float* b_out  = (const float*)d_in[16];
  const float* W_eout = (const float*)d_in[17]; const float* b_eout = (const float*)d_in[18];
  const float* g1     = (const float*)d_in[19]; const float* be1    = (const float*)d_in[20];
  const float* g2     = (const float*)d_in[21]; const float* be2    = (const float*)d_in[22];

  float* outH = (float*)d_out;
  float* outE = outH + HROWS*HIDn;

  cudaFuncSetAttribute(k_edge_attn_mma, cudaFuncAttributeMaxDynamicSharedMemorySize, EA_SMEM);
  cudaFuncSetAttribute(k_attn2, cudaFuncAttributeMaxDynamicSharedMemorySize, 128*1024);

  int attn_smem = (IPB*128 + IPB*128 + 64*KPAD + IPB*8*Nn) * 4;

  k_lin_h0<<<HROWS/8, 128>>>(node, W_node, b_node);
  k_qkv<<<HROWS/8, 128>>>(W_q, b_q, W_k, b_k, W_v, b_v);
  k_edge_attn_mma<<<EA_GRID, 256, EA_SMEM>>>(edge, W_edge, W_gate, b_edge, b_gate);
  k_attn2<<<HROWS/IPB, 256, attn_smem>>>(adj);
  k_hout<<<HROWS, 128>>>(W_out, b_out, g1, be1, W_eout, outH);
  k_edge_out<<<EROWS/8, 256>>>(edge, b_eout, g2, be2, outE);
}

// round 6
// speedup vs baseline: 2.8455x; 1.0224x over previous
#include <cuda_runtime.h>
#include <cstdint>
#include <math.h>

#define Bn    2
#define Nn    384
#define HIDn  128
#define NHn   8
#define HDn   16
#define HROWS (Bn*Nn)          // 768
#define EROWS (Bn*Nn*Nn)       // 294912

// ---------------- scratch (static device globals; no allocations) ----------------
__device__ float g_h0[HROWS*HIDn];
__device__ float g_Q[HROWS*HIDn];
__device__ float g_K[HROWS*HIDn];
__device__ float g_V[HROWS*HIDn];
__device__ float g_eatt[(size_t)EROWS*NHn];   // (b,i,j,h) contiguous h
__device__ float g_amean[EROWS];
__device__ float g_attO[HROWS*HIDn];
__device__ float g_hW[HROWS*HIDn];

// ================= helpers =================
__device__ __forceinline__ float sigm(float x) { return 1.f / (1.f + __expf(-x)); }
__device__ __forceinline__ uint32_t pack_half2(float lo, float hi) {
  uint32_t r;
  asm("cvt.rn.f16x2.f32 %0, %1, %2;" : "=r"(r) : "f"(hi), "f"(lo));
  return r;
}
__device__ __forceinline__ void mma16(float* d, const uint4 a, const uint2 b) {
  asm volatile("mma.sync.aligned.m16n8k16.row.col.f32.f16.f16.f32 "
    "{%0,%1,%2,%3},{%4,%5,%6,%7},{%8,%9},{%0,%1,%2,%3};"
    : "+f"(d[0]), "+f"(d[1]), "+f"(d[2]), "+f"(d[3])
    : "r"(a.x), "r"(a.y), "r"(a.z), "r"(a.w), "r"(b.x), "r"(b.y));
}
__device__ __forceinline__ uint32_t smem_u32(const void* p) {
  uint32_t a;
  asm("{ .reg .u64 t; cvta.to.shared.u64 t, %1; cvt.u32.u64 %0, t; }" : "=r"(a) : "l"(p));
  return a;
}
__device__ __forceinline__ void cpa16(uint32_t dst, const void* src) {
  asm volatile("cp.async.cg.shared.global [%0], [%1], 16;" :: "r"(dst), "l"(src));
}
#define CPA_COMMIT() asm volatile("cp.async.commit_group;" ::: "memory")
#define CPA_WAIT0()  asm volatile("cp.async.wait_group 0;" ::: "memory")

// ---------------- kernel 1: h0 = node @ W_node + b_node ----------------
__global__ void k_lin_h0(const float* __restrict__ X, const float* __restrict__ W,
                         const float* __restrict__ bias) {
  int d = threadIdx.x;
  int r0 = blockIdx.x * 8;
  __shared__ float sX[8*128];
  for (int idx = d; idx < 8*128; idx += 128) sX[idx] = X[r0*128 + idx];
  __syncthreads();
  float acc[8];
  float bv = bias[d];
#pragma unroll
  for (int r = 0; r < 8; r++) acc[r] = bv;
  for (int k = 0; k < 128; k++) {
    float w = W[k*128 + d];
#pragma unroll
    for (int r = 0; r < 8; r++) acc[r] += sX[r*128 + k] * w;
  }
#pragma unroll
  for (int r = 0; r < 8; r++) g_h0[(r0 + r)*128 + d] = acc[r];
}

// ---------------- kernel 2: Q,K,V ----------------
__global__ void k_qkv(const float* __restrict__ Wq, const float* __restrict__ bq,
                      const float* __restrict__ Wk, const float* __restrict__ bk,
                      const float* __restrict__ Wv, const float* __restrict__ bv) {
  int d = threadIdx.x;
  int r0 = blockIdx.x * 8;
  __shared__ float sX[8*128];
  for (int idx = d; idx < 8*128; idx += 128) sX[idx] = g_h0[r0*128 + idx];
  __syncthreads();
  float aq[8], ak[8], av[8];
  float bqv = bq[d], bkv = bk[d], bvv = bv[d];
#pragma unroll
  for (int r = 0; r < 8; r++) { aq[r] = bqv; ak[r] = bkv; av[r] = bvv; }
  for (int k = 0; k < 128; k++) {
    float wq = Wq[k*128 + d], wk = Wk[k*128 + d], wv = Wv[k*128 + d];
#pragma unroll
    for (int r = 0; r < 8; r++) {
      float x = sX[r*128 + k];
      aq[r] += x*wq; ak[r] += x*wk; av[r] += x*wv;
    }
  }
#pragma unroll
  for (int r = 0; r < 8; r++) {
    g_Q[(r0 + r)*128 + d] = aq[r];
    g_K[(r0 + r)*128 + d] = ak[r];
    g_V[(r0 + r)*128 + d] = av[r];
  }
}

// ---------------- kernel 3: edge_attn via fp16 m16n8k16 mma.sync ----------------
// warp = head. B fragments (We+Wg, this head's 16 columns) live in registers.
// Mainloop per ks: 4 independent LDS.128 (A frags) -> 16 independent MMAs.
#define EA_GRID 144
#define EA_TPC  16
#define RAW_STRIDE  132
// smem: sA 32KB | raw 67584B | bias 1KB
#define EA_OFF_RAW  32768
#define EA_OFF_BIAS (32768 + 67584)
#define EA_SMEM     (EA_OFF_BIAS + 1024)

__global__ void __launch_bounds__(256, 1) k_edge_attn_mma(
    const float* __restrict__ E,
    const float* __restrict__ We, const float* __restrict__ Wg,
    const float* __restrict__ be, const float* __restrict__ bg) {
  extern __shared__ char smem[];
  uint4* sA4   = (uint4*)smem;                    // [(ks*8+mt)*32+lane]
  float* raw   = (float*)(smem + EA_OFF_RAW);     // [128][RAW_STRIDE]
  float* sBias = (float*)(smem + EA_OFF_BIAS);    // be | bg
  uint32_t rawu = smem_u32(raw);

  int tid = threadIdx.x;
  int h = tid >> 5, lane = tid & 31;              // warp == head
  int g = lane >> 2, t4 = lane & 3;

  if (tid < 128) { sBias[tid] = be[tid]; sBias[128 + tid] = bg[tid]; }

  // ---- load B fragments into registers (staged via raw for coalescing) ----
  uint2 Bf[2][2][8];     // [EG][nti][ks]
#pragma unroll
  for (int half = 0; half < 2; half++) {
    const float* W = half ? Wg : We;
    __syncthreads();
    for (int idx = tid; idx < 128*32; idx += 256) {
      int k = idx >> 5, c4 = idx & 31;
      float4 v = ((const float4*)W)[idx];
      *(float4*)(raw + k*RAW_STRIDE + c4*4) = v;
    }
    __syncthreads();
#pragma unroll
    for (int nti = 0; nti < 2; nti++) {
      int n = (2*h + nti)*8 + g;
#pragma unroll
      for (int ks = 0; ks < 8; ks++) {
        int k0 = ks*16 + 2*t4;
        uint32_t b0 = pack_half2(raw[k0*RAW_STRIDE + n],     raw[(k0+1)*RAW_STRIDE + n]);
        uint32_t b1 = pack_half2(raw[(k0+8)*RAW_STRIDE + n], raw[(k0+9)*RAW_STRIDE + n]);
        Bf[half][nti][ks] = make_uint2(b0, b1);
      }
    }
  }
  __syncthreads();   // raw free for E tiles

  // ---- pipeline: prefetch tile 0 ----
  {
    const float* Eg = E + ((size_t)blockIdx.x * EA_TPC) * 128 * 128;
    for (int idx = tid; idx < 4096; idx += 256) {
      int m = idx >> 5, c4 = idx & 31;
      cpa16(rawu + (uint32_t)(m*RAW_STRIDE + c4*4)*4u, Eg + m*128 + c4*4);
    }
    CPA_COMMIT();
  }

  for (int t = 0; t < EA_TPC; t++) {
    size_t rowBase = ((size_t)blockIdx.x * EA_TPC + t) * 128;
    CPA_WAIT0();
    __syncthreads();   // raw ready; previous compute done with sA

    // convert raw fp32 -> fragment-order fp16 sA
#pragma unroll
    for (int it = 0; it < 8; it++) {
      int idx = tid + it*256;                 // 0..2047
      int lf = idx & 31, mt = (idx >> 5) & 7, ks = idx >> 8;
      int gg = lf >> 2, tt = lf & 3;
      int m0 = mt*16 + gg;
      int k0 = ks*16 + 2*tt;
      float2 x0 = *(float2*)(raw + m0*RAW_STRIDE + k0);
      float2 x1 = *(float2*)(raw + (m0+8)*RAW_STRIDE + k0);
      float2 x2 = *(float2*)(raw + m0*RAW_STRIDE + k0 + 8);
      float2 x3 = *(float2*)(raw + (m0+8)*RAW_STRIDE + k0 + 8);
      uint4 v;
      v.x = pack_half2(x0.x, x0.y);
      v.y = pack_half2(x1.x, x1.y);
      v.z = pack_half2(x2.x, x2.y);
      v.w = pack_half2(x3.x, x3.y);
      sA4[idx] = v;
    }
    __syncthreads();   // sA ready; raw free

    if (t + 1 < EA_TPC) {
      const float* Eg = E + (rowBase + 128) * 128;
      for (int idx = tid; idx < 4096; idx += 256) {
        int m = idx >> 5, c4 = idx & 31;
        cpa16(rawu + (uint32_t)(m*RAW_STRIDE + c4*4)*4u, Eg + m*128 + c4*4);
      }
      CPA_COMMIT();
    }

    // ---- compute: two groups of 4 m-tiles; all-register B ----
#pragma unroll
    for (int grp = 0; grp < 2; grp++) {
      float aE[4][2][4], aG[4][2][4];
#pragma unroll
      for (int m4 = 0; m4 < 4; m4++)
#pragma unroll
        for (int nti = 0; nti < 2; nti++)
#pragma unroll
          for (int r = 0; r < 4; r++) { aE[m4][nti][r] = 0.f; aG[m4][nti][r] = 0.f; }

#pragma unroll
      for (int ks = 0; ks < 8; ks++) {
        uint4 a[4];
#pragma unroll
        for (int m4 = 0; m4 < 4; m4++)
          a[m4] = sA4[(ks*8 + grp*4 + m4)*32 + lane];
#pragma unroll
        for (int m4 = 0; m4 < 4; m4++) {
#pragma unroll
          for (int nti = 0; nti < 2; nti++) {
            mma16(aE[m4][nti], a[m4], Bf[0][nti][ks]);
            mma16(aG[m4][nti], a[m4], Bf[1][nti][ks]);
          }
        }
      }

      // epilogue: bias + sigmoid gate + per-head reduce over 16 dims
#pragma unroll
      for (int m4 = 0; m4 < 4; m4++) {
        int mt = grp*4 + m4;
        float s0 = 0.f, s1 = 0.f;
#pragma unroll
        for (int nti = 0; nti < 2; nti++) {
          int nb = (2*h + nti)*8 + 2*t4;
          float be0 = sBias[nb], be1 = sBias[nb+1];
          float bg0 = sBias[128+nb], bg1 = sBias[128+nb+1];
          s0 += (aE[m4][nti][0] + be0) * sigm(aG[m4][nti][0] + bg0)
              + (aE[m4][nti][1] + be1) * sigm(aG[m4][nti][1] + bg1);
          s1 += (aE[m4][nti][2] + be0) * sigm(aG[m4][nti][2] + bg0)
              + (aE[m4][nti][3] + be1) * sigm(aG[m4][nti][3] + bg1);
        }
        s0 += __shfl_xor_sync(0xffffffffu, s0, 1);
        s0 += __shfl_xor_sync(0xffffffffu, s0, 2);
        s1 += __shfl_xor_sync(0xffffffffu, s1, 1);
        s1 += __shfl_xor_sync(0xffffffffu, s1, 2);
        if (t4 == 0) {
          size_t r0 = rowBase + (size_t)mt*16 + g;
          g_eatt[r0*8 + h]       = s0;
          g_eatt[(r0 + 8)*8 + h] = s1;
        }
      }
    }
  }
}

// ---------------- kernel 4: scores + softmax + attn_mean + attn_out (tiled) ----------------
#define IPB 2
#define KPAD 132
__global__ void __launch_bounds__(256) k_attn2(const int* __restrict__ adj) {
  extern __shared__ float sm2[];
  float* sQ    = sm2;                   // IPB*128
  float* sPart = sQ + IPB*128;          // IPB*128
  float* sKV   = sPart + IPB*128;       // 64*KPAD
  float* sAtt  = sKV + 64*KPAD;         // IPB*8*Nn
  int tid = threadIdx.x;
  int bi0 = blockIdx.x * IPB;
  int b = bi0 / Nn;

  for (int idx = tid; idx < IPB*128; idx += 256) sQ[idx] = g_Q[bi0*128 + idx];
  __syncthreads();

  int jl = tid & 63, hp = tid >> 6;
  int h0 = hp*2;
  for (int jt = 0; jt < Nn/64; jt++) {
    for (int idx = tid; idx < 64*32; idx += 256) {
      int r = idx >> 5, c4 = idx & 31;
      float4 v = ((const float4*)(g_K + (size_t)(b*Nn + jt*64)*128))[idx];
      *(float4*)(sKV + r*KPAD + c4*4) = v;
    }
    __syncthreads();
    int j = jt*64 + jl;
    const float* kr = sKV + jl*KPAD;
    float a0[IPB], a1[IPB];
#pragma unroll
    for (int q = 0; q < IPB; q++) { a0[q] = 0.f; a1[q] = 0.f; }
#pragma unroll
    for (int d = 0; d < 16; d++) {
      float k0 = kr[h0*16 + d], k1 = kr[h0*16 + 16 + d];
#pragma unroll
      for (int q = 0; q < IPB; q++) {
        a0[q] += sQ[q*128 + h0*16 + d]      * k0;
        a1[q] += sQ[q*128 + h0*16 + 16 + d] * k1;
      }
    }
#pragma unroll
    for (int q = 0; q < IPB; q++) {
      int bi = bi0 + q;
      const float* er = g_eatt + ((size_t)bi*Nn + j)*8 + h0;
      float sc0 = a0[q]*0.25f + er[0];
      float sc1 = a1[q]*0.25f + er[1];
      if (adj[(size_t)bi*Nn + j] == 0) { sc0 = -1e9f; sc1 = -1e9f; }
      sAtt[(q*8 + h0)*Nn + j]     = sc0;
      sAtt[(q*8 + h0 + 1)*Nn + j] = sc1;
    }
    __syncthreads();
  }

  {
    int w = tid >> 5, lane = tid & 31;
    if (w < NHn) {
      for (int q = 0; q < IPB; q++) {
        float* rowp = sAtt + (q*8 + w)*Nn;
        float vals[12];
        float m = -1e30f;
#pragma unroll
        for (int c = 0; c < 12; c++) { vals[c] = rowp[lane + c*32]; m = fmaxf(m, vals[c]); }
#pragma unroll
        for (int off = 16; off > 0; off >>= 1) m = fmaxf(m, __shfl_xor_sync(0xffffffffu, m, off));
        float s = 0.f;
#pragma unroll
        for (int c = 0; c < 12; c++) { vals[c] = __expf(vals[c] - m); s += vals[c]; }
#pragma unroll
        for (int off = 16; off > 0; off >>= 1) s += __shfl_xor_sync(0xffffffffu, s, off);
        float inv = 1.f / s;
#pragma unroll
        for (int c = 0; c < 12; c++) rowp[lane + c*32] = vals[c] * inv;
      }
    }
  }
  __syncthreads();

  for (int idx = tid; idx < IPB*Nn; idx += 256) {
    int q = idx / Nn, j = idx % Nn;
    float s = 0.f;
#pragma unroll
    for (int h = 0; h < 8; h++) s += sAtt[(q*8 + h)*Nn + j];
    g_amean[(size_t)(bi0 + q)*Nn + j] = s * (1.f/NHn);
  }

  int d = tid & 127, half = tid >> 7;
  int hc = d >> 4;
  float acc[IPB];
#pragma unroll
  for (int q = 0; q < IPB; q++) acc[q] = 0.f;
  for (int jt = 0; jt < Nn/64; jt++) {
    __syncthreads();
    for (int idx = tid; idx < 64*32; idx += 256) {
      int r = idx >> 5, c4 = idx & 31;
      float4 v = ((const float4*)(g_V + (size_t)(b*Nn + jt*64)*128))[idx];
      *(float4*)(sKV + r*KPAD + c4*4) = v;
    }
    __syncthreads();
#pragma unroll 8
    for (int jj = half*32; jj < half*32 + 32; jj++) {
      float v = sKV[jj*KPAD + d];
      int j = jt*64 + jj;
#pragma unroll
      for (int q = 0; q < IPB; q++) acc[q] += sAtt[(q*8 + hc)*Nn + j] * v;
    }
  }
  __syncthreads();
  if (half == 1) {
#pragma unroll
    for (int q = 0; q < IPB; q++) sPart[q*128 + d] = acc[q];
  }
  __syncthreads();
  if (half == 0) {
#pragma unroll
    for (int q = 0; q < IPB; q++)
      g_attO[(size_t)(bi0 + q)*128 + d] = acc[q] + sPart[q*128 + d];
  }
}

// ---------------- kernel 5: h = LN(h0 + attO@W_out + b_out); hW = h @ W_eout ----------------
__global__ void k_hout(const float* __restrict__ Wout, const float* __restrict__ bout,
                       const float* __restrict__ g1, const float* __restrict__ be1,
                       const float* __restrict__ Weout, float* __restrict__ outH) {
  int row = blockIdx.x;
  int d = threadIdx.x;
  int lane = d & 31, w = d >> 5;
  __shared__ float sIn[128];
  __shared__ float sRow[128];
  __shared__ float sS[4], sQ2[4];
  sIn[d] = g_attO[row*128 + d];
  __syncthreads();
  float acc = bout[d];
#pragma unroll 4
  for (int k = 0; k < 128; k++) acc += sIn[k] * Wout[k*128 + d];
  float r = acc + g_h0[row*128 + d];
  float v = r, q = r*r;
#pragma unroll
  for (int off = 16; off > 0; off >>= 1) {
    v += __shfl_xor_sync(0xffffffffu, v, off);
    q += __shfl_xor_sync(0xffffffffu, q, off);
  }
  if (lane == 0) { sS[w] = v; sQ2[w] = q; }
  __syncthreads();
  float tot  = sS[0] + sS[1] + sS[2] + sS[3];
  float totq = sQ2[0] + sQ2[1] + sQ2[2] + sQ2[3];
  float mean = tot * (1.f/128.f);
  float var  = totq * (1.f/128.f) - mean*mean;
  float y = (r - mean) * rsqrtf(var + 1e-5f) * g1[d] + be1[d];
  outH[row*128 + d] = y;
  sRow[d] = y;
  __syncthreads();
  float acc2 = 0.f;
#pragma unroll 4
  for (int k = 0; k < 128; k++) acc2 += sRow[k] * Weout[k*128 + d];
  g_hW[row*128 + d] = acc2;
}

// ---------------- kernel 6: edge_out = LN(E + amean*0.5*(hW_i+hW_j) + b_eout) ----------------
__global__ void k_edge_out(const float* __restrict__ Ef, const float* __restrict__ beout,
                           const float* __restrict__ g2, const float* __restrict__ be2,
                           float* __restrict__ outE) {
  int warp = threadIdx.x >> 5, lane = threadIdx.x & 31;
  size_t row = (size_t)blockIdx.x * 8 + warp;
  int b  = (int)(row / (Nn*Nn));
  int ij = (int)(row % (Nn*Nn));
  int i = ij / Nn, j = ij % Nn;
  float am = g_amean[row] * 0.5f;
  float4 e  = ((const float4*)(Ef + row*128))[lane];
  float4 ui = ((const float4*)(g_hW + (size_t)(b*Nn + i)*128))[lane];
  float4 uj = ((const float4*)(g_hW + (size_t)(b*Nn + j)*128))[lane];
  float4 bo = ((const float4*)beout)[lane];
  float v0 = e.x + am*(ui.x + uj.x) + bo.x;
  float v1 = e.y + am*(ui.y + uj.y) + bo.y;
  float v2 = e.z + am*(ui.z + uj.z) + bo.z;
  float v3 = e.w + am*(ui.w + uj.w) + bo.w;
  float s = v0 + v1 + v2 + v3;
  float q = v0*v0 + v1*v1 + v2*v2 + v3*v3;
#pragma unroll
  for (int off = 16; off > 0; off >>= 1) {
    s += __shfl_xor_sync(0xffffffffu, s, off);
    q += __shfl_xor_sync(0xffffffffu, q, off);
  }
  float mean = s * (1.f/128.f);
  float var  = q * (1.f/128.f) - mean*mean;
  float inv  = rsqrtf(var + 1e-5f);
  float4 gg = ((const float4*)g2)[lane];
  float4 bb = ((const float4*)be2)[lane];
  float4 o;
  o.x = (v0 - mean)*inv*gg.x + bb.x;
  o.y = (v1 - mean)*inv*gg.y + bb.y;
  o.z = (v2 - mean)*inv*gg.z + bb.z;
  o.w = (v3 - mean)*inv*gg.w + bb.w;
  ((float4*)outE)[row*32 + lane] = o;
}

// ---------------- launcher ----------------
extern "C" void kernel_launch(void* const* d_in, const int* in_sizes, int n_in,
                              void* d_out, int out_size) {
  const float* node   = (const float*)d_in[0];
  const float* edge   = (const float*)d_in[1];
  const int*   adj    = (const int*)  d_in[2];
  const float* W_node = (const float*)d_in[3];  const float* b_node = (const float*)d_in[4];
  const float* W_q    = (const float*)d_in[5];  const float* b_q    = (const float*)d_in[6];
  const float* W_k    = (const float*)d_in[7];  const float* b_k    = (const float*)d_in[8];
  const float* W_v    = (const float*)d_in[9];  const float* b_v    = (const float*)d_in[10];
  const float* W_edge = (const float*)d_in[11]; const float* b_edge = (const float*)d_in[12];
  const float* W_gate = (const float*)d_in[13]; const float* b_gate = (const float*)d_in[14];
  const float* W_out  = (const float*)d_in[15]; const float* b_out  = (const float*)d_in[16];
  const float* W_eout = (const float*)d_in[17]; const float* b_eout = (const float*)d_in[18];
  const float* g1     = (const float*)d_in[19]; const float* be1    = (const float*)d_in[20];
  const float* g2     = (const float*)d_in[21]; const float* be2    = (const float*)d_in[22];

  float* outH = (float*)d_out;
  float* outE = outH + HROWS*HIDn;

  cudaFuncSetAttribute(k_edge_attn_mma, cudaFuncAttributeMaxDynamicSharedMemorySize, EA_SMEM);
  cudaFuncSetAttribute(k_attn2, cudaFuncAttributeMaxDynamicSharedMemorySize, 128*1024);

  int attn_smem = (IPB*128 + IPB*128 + 64*KPAD + IPB*8*Nn) * 4;

  k_lin_h0<<<HROWS/8, 128>>>(node, W_node, b_node);
  k_qkv<<<HROWS/8, 128>>>(W_q, b_q, W_k, b_k, W_v, b_v);
  k_edge_attn_mma<<<EA_GRID, 256, EA_SMEM>>>(edge, W_edge, W_gate, b_edge, b_gate);
  k_attn2<<<HROWS/IPB, 256, attn_smem>>>(adj);
  k_hout<<<HROWS, 128>>>(W_out, b_out, g1, be1, W_eout, outH);
  k_edge_out<<<EROWS/8, 256>>>(edge, b_eout, g2, be2, outE);
}